// round 3
// baseline (speedup 1.0000x reference)
#include <cuda_runtime.h>
#include <cstdint>

// Fused retention-block kernel.
// One CTA per location n (N=8192 CTAs), 256 threads, 2 CTAs/SM.
// Per-CTA pipeline in SMEM: x-tile -> QKV GEMMs -> rotary -> attention
// (decay-masked softmax over S=32) -> +res LN1 -> FFN (hidden processed in
// 128-col blocks, FFN2 accumulated in registers) -> +res LN2 -> out.

#define TS 132            // 32-row tile stride (pad 128 -> 132 floats)
#define TPB 256

__device__ __forceinline__ float4 ld4(const float* p) { return *(const float4*)p; }

// Accumulate: acc[4][4] += As[r0..r0+3][0..K) * W[0..K)[c0..c0+3]  (W row stride LDW)
template<int K, int LDW>
__device__ __forceinline__ void gemm_acc(
    const float* __restrict__ As, int lda,
    const float* __restrict__ W, int c0, int r0,
    float acc[4][4])
{
#pragma unroll 2
    for (int k = 0; k < K; k += 4) {
        float4 a0 = ld4(&As[(r0 + 0) * lda + k]);
        float4 a1 = ld4(&As[(r0 + 1) * lda + k]);
        float4 a2 = ld4(&As[(r0 + 2) * lda + k]);
        float4 a3 = ld4(&As[(r0 + 3) * lda + k]);
#pragma unroll
        for (int kk = 0; kk < 4; kk++) {
            float4 w = ld4(&W[(k + kk) * LDW + c0]);
            float a[4] = { ((const float*)&a0)[kk], ((const float*)&a1)[kk],
                           ((const float*)&a2)[kk], ((const float*)&a3)[kk] };
#pragma unroll
            for (int i = 0; i < 4; i++) {
                acc[i][0] += a[i] * w.x; acc[i][1] += a[i] * w.y;
                acc[i][2] += a[i] * w.z; acc[i][3] += a[i] * w.w;
            }
        }
    }
}

// Full 32x128-slice GEMM with bias (+optional relu) written to SMEM.
template<int K, int LDW>
__device__ __forceinline__ void gemm_32xN(
    const float* __restrict__ As, int lda,
    const float* __restrict__ W,
    const float* __restrict__ bias, int colbase,
    float* __restrict__ Os, int ldo,
    bool relu, int tr, int tc)
{
    const int r0 = tr * 4;
    const int c0 = colbase + tc * 4;
    float4 bv = ld4(&bias[c0]);
    float acc[4][4];
#pragma unroll
    for (int i = 0; i < 4; i++) {
        acc[i][0] = bv.x; acc[i][1] = bv.y; acc[i][2] = bv.z; acc[i][3] = bv.w;
    }
    gemm_acc<K, LDW>(As, lda, W, c0, r0, acc);
#pragma unroll
    for (int i = 0; i < 4; i++) {
        float4 o;
        o.x = acc[i][0]; o.y = acc[i][1]; o.z = acc[i][2]; o.w = acc[i][3];
        if (relu) {
            o.x = fmaxf(o.x, 0.f); o.y = fmaxf(o.y, 0.f);
            o.z = fmaxf(o.z, 0.f); o.w = fmaxf(o.w, 0.f);
        }
        *(float4*)&Os[(r0 + i) * ldo + tc * 4] = o;   // Os indexed by local col
    }
}

extern "C" __global__ void __launch_bounds__(TPB, 2)
retention_block_kernel(
    const float* __restrict__ x,
    const float* __restrict__ wq, const float* __restrict__ bq,
    const float* __restrict__ wk, const float* __restrict__ bk,
    const float* __restrict__ wv, const float* __restrict__ bv,
    const float* __restrict__ ln1g, const float* __restrict__ ln1b,
    const float* __restrict__ w1, const float* __restrict__ b1,
    const float* __restrict__ w2, const float* __restrict__ b2,
    const float* __restrict__ ln2g, const float* __restrict__ ln2b,
    float* __restrict__ out, int N)
{
    extern __shared__ float sm[];
    float* xs  = sm;                 // 32 x TS : x rows (residual 1)
    float* ta  = xs  + 32 * TS;      // q  -> attn_out
    float* tb  = ta  + 32 * TS;      // k  -> LN1 out (h0, residual 2)
    float* tcm = tb  + 32 * TS;      // v  -> ffn2 out
    float* hb  = tcm + 32 * TS;      // 32 x TS : FFN hidden block (reused 4x)

    const int t  = threadIdx.x;
    const int n  = blockIdx.x;
    const int tr = t >> 5, tc = t & 31;

    // ---- load x tile: xs[s][c] = x[s][n][c] ----
    {
        const float4* xg = (const float4*)x;
        for (int idx = t; idx < 32 * 32; idx += TPB) {
            int r = idx >> 5, c4 = idx & 31;
            float4 v = xg[((size_t)r * N + n) * 32 + c4];
            *(float4*)&xs[r * TS + c4 * 4] = v;
        }
    }
    __syncthreads();

    // ---- QKV projections ----
    gemm_32xN<128, 128>(xs, TS, wq, bq, 0, ta,  TS, false, tr, tc);
    gemm_32xN<128, 128>(xs, TS, wk, bk, 0, tb,  TS, false, tr, tc);
    gemm_32xN<128, 128>(xs, TS, wv, bv, 0, tcm, TS, false, tr, tc);
    __syncthreads();

    // ---- rotary on q (ta) and k (tb); each (row, head) owned by one thread ----
    {
        int r = t >> 3, h = t & 7;   // row 0..31, head 0..7
        const float l2c = 13.287712379549449f / 7.0f;   // log2(10000)/7
        float sn[16], cs[16];
#pragma unroll
        for (int d = 0; d < 16; d++) {
            float ang = exp2f(-(float)(d >> 1) * l2c);
            float ph = (float)r * ang;
            sn[d] = sinf(ph); cs[d] = cosf(ph);
        }
#pragma unroll
        for (int which = 0; which < 2; which++) {
            float* bp = (which == 0 ? ta : tb) + r * TS + h * 16;
            float tv[16];
#pragma unroll
            for (int d = 0; d < 16; d++) tv[d] = bp[d];
#pragma unroll
            for (int d = 0; d < 8; d++)  bp[d] = tv[d] * cs[d] - tv[2 * d + 1]   * sn[d];
#pragma unroll
            for (int d = 8; d < 16; d++) bp[d] = tv[d] * cs[d] + tv[2 * (d - 8)] * sn[d];
        }
    }
    __syncthreads();

    // ---- attention: warp h handles head h, lane i = query row ----
    {
        int h = t >> 5, qi = t & 31;
        float qr[16];
#pragma unroll
        for (int d4 = 0; d4 < 4; d4++) {
            float4 v = ld4(&ta[qi * TS + h * 16 + d4 * 4]);
            qr[d4 * 4 + 0] = v.x; qr[d4 * 4 + 1] = v.y;
            qr[d4 * 4 + 2] = v.z; qr[d4 * 4 + 3] = v.w;
        }
        __syncthreads();   // ta now free -> attn_out destination

        float dec = log1pf(-exp2f(-(1.0f + 0.375f * (float)h)));
        float sc[32];
#pragma unroll
        for (int j = 0; j < 32; j++) {
            const float* kp = &tb[j * TS + h * 16];
            float s = fabsf((float)(qi - j)) * dec;
#pragma unroll
            for (int d4 = 0; d4 < 4; d4++) {
                float4 kv = ld4(kp + d4 * 4);
                s += qr[d4 * 4 + 0] * kv.x + qr[d4 * 4 + 1] * kv.y
                   + qr[d4 * 4 + 2] * kv.z + qr[d4 * 4 + 3] * kv.w;
            }
            sc[j] = s;
        }
        float m = sc[0];
#pragma unroll
        for (int j = 1; j < 32; j++) m = fmaxf(m, sc[j]);
        float sum = 0.f;
#pragma unroll
        for (int j = 0; j < 32; j++) { sc[j] = __expf(sc[j] - m); sum += sc[j]; }
        float inv = 1.0f / sum;
        float o[16];
#pragma unroll
        for (int d = 0; d < 16; d++) o[d] = 0.f;
#pragma unroll
        for (int j = 0; j < 32; j++) {
            const float* vp = &tcm[j * TS + h * 16];
            float p = sc[j];
#pragma unroll
            for (int d4 = 0; d4 < 4; d4++) {
                float4 vv = ld4(vp + d4 * 4);
                o[d4 * 4 + 0] += p * vv.x; o[d4 * 4 + 1] += p * vv.y;
                o[d4 * 4 + 2] += p * vv.z; o[d4 * 4 + 3] += p * vv.w;
            }
        }
#pragma unroll
        for (int d = 0; d < 16; d++) ta[qi * TS + h * 16 + d] = o[d] * inv;
    }
    __syncthreads();

    // ---- LN1: h0 = LN(attn_out + x) -> tb ----
    {
        int w = t >> 5, l = t & 31;
        for (int r = w; r < 32; r += 8) {
            float4 a  = ld4(&ta[r * TS + 4 * l]);
            float4 xv = ld4(&xs[r * TS + 4 * l]);
            float v0 = a.x + xv.x, v1 = a.y + xv.y, v2 = a.z + xv.z, v3 = a.w + xv.w;
            float s  = v0 + v1 + v2 + v3;
            float s2 = v0 * v0 + v1 * v1 + v2 * v2 + v3 * v3;
#pragma unroll
            for (int off = 16; off; off >>= 1) {
                s  += __shfl_xor_sync(0xffffffffu, s,  off);
                s2 += __shfl_xor_sync(0xffffffffu, s2, off);
            }
            float mu  = s * (1.f / 128.f);
            float var = s2 * (1.f / 128.f) - mu * mu;
            float rs  = rsqrtf(var + 1e-5f);
            float4 gg = ld4(&ln1g[4 * l]);
            float4 bb = ld4(&ln1b[4 * l]);
            float4 o;
            o.x = (v0 - mu) * rs * gg.x + bb.x; o.y = (v1 - mu) * rs * gg.y + bb.y;
            o.z = (v2 - mu) * rs * gg.z + bb.z; o.w = (v3 - mu) * rs * gg.w + bb.w;
            *(float4*)&tb[r * TS + 4 * l] = o;
        }
    }
    __syncthreads();

    // ---- FFN fused: for each 128-col hidden block, compute relu(h0@w1+b1)
    //      into hb, then accumulate hb @ w2-block into register acc ----
    {
        const int r0 = tr * 4, c0 = tc * 4;
        float4 b2v = ld4(&b2[c0]);
        float acc[4][4];
#pragma unroll
        for (int i = 0; i < 4; i++) {
            acc[i][0] = b2v.x; acc[i][1] = b2v.y; acc[i][2] = b2v.z; acc[i][3] = b2v.w;
        }
        for (int cb = 0; cb < 4; cb++) {
            gemm_32xN<128, 512>(tb, TS, w1, b1, cb * 128, hb, TS, true, tr, tc);
            __syncthreads();
            gemm_acc<128, 128>(hb, TS, w2 + cb * 128 * 128, c0, r0, acc);
            __syncthreads();   // before hb is overwritten next iter
        }
#pragma unroll
        for (int i = 0; i < 4; i++) {
            float4 o;
            o.x = acc[i][0]; o.y = acc[i][1]; o.z = acc[i][2]; o.w = acc[i][3];
            *(float4*)&tcm[(r0 + i) * TS + c0] = o;
        }
    }
    __syncthreads();

    // ---- LN2: out = LN(ffn + h0), store transposed (s, n, c) ----
    {
        int w = t >> 5, l = t & 31;
        for (int r = w; r < 32; r += 8) {
            float4 a  = ld4(&tcm[r * TS + 4 * l]);
            float4 hv = ld4(&tb[r * TS + 4 * l]);
            float v0 = a.x + hv.x, v1 = a.y + hv.y, v2 = a.z + hv.z, v3 = a.w + hv.w;
            float s  = v0 + v1 + v2 + v3;
            float s2 = v0 * v0 + v1 * v1 + v2 * v2 + v3 * v3;
#pragma unroll
            for (int off = 16; off; off >>= 1) {
                s  += __shfl_xor_sync(0xffffffffu, s,  off);
                s2 += __shfl_xor_sync(0xffffffffu, s2, off);
            }
            float mu  = s * (1.f / 128.f);
            float var = s2 * (1.f / 128.f) - mu * mu;
            float rs  = rsqrtf(var + 1e-5f);
            float4 gg = ld4(&ln2g[4 * l]);
            float4 bb = ld4(&ln2b[4 * l]);
            float4 o;
            o.x = (v0 - mu) * rs * gg.x + bb.x; o.y = (v1 - mu) * rs * gg.y + bb.y;
            o.z = (v2 - mu) * rs * gg.z + bb.z; o.w = (v3 - mu) * rs * gg.w + bb.w;
            *(float4*)&out[((size_t)r * N + n) * 128 + 4 * l] = o;
        }
    }
}

static const int SMEM_BYTES = (5 * 32 * TS) * (int)sizeof(float);  // 84480

extern "C" void kernel_launch(void* const* d_in, const int* in_sizes, int n_in,
                              void* d_out, int out_size)
{
    const float* x    = (const float*)d_in[0];
    const float* wq   = (const float*)d_in[1];
    const float* bq   = (const float*)d_in[2];
    const float* wk   = (const float*)d_in[3];
    const float* bk   = (const float*)d_in[4];
    const float* wv   = (const float*)d_in[5];
    const float* bv   = (const float*)d_in[6];
    const float* ln1g = (const float*)d_in[7];
    const float* ln1b = (const float*)d_in[8];
    const float* w1   = (const float*)d_in[9];
    const float* b1   = (const float*)d_in[10];
    const float* w2   = (const float*)d_in[11];
    const float* b2   = (const float*)d_in[12];
    const float* ln2g = (const float*)d_in[13];
    const float* ln2b = (const float*)d_in[14];
    float* out = (float*)d_out;

    int N = in_sizes[0] / (32 * 128);   // B=32, C=128 fixed; N from x element count

    // Idempotent + deterministic on every call (no static guards; not a
    // stream-ordered op, so safe under graph capture).
    cudaFuncSetAttribute(retention_block_kernel,
                         cudaFuncAttributeMaxDynamicSharedMemorySize, SMEM_BYTES);

    retention_block_kernel<<<N, TPB, SMEM_BYTES>>>(
        x, wq, bq, wk, bk, wv, bv, ln1g, ln1b,
        w1, b1, w2, b2, ln2g, ln2b, out, N);
}

// round 6
// speedup vs baseline: 1.0001x; 1.0001x over previous
#include <cuda_runtime.h>
#include <cstdint>

// Fused retention-block kernel.
// One CTA per location n (N=8192 CTAs), 256 threads, 2 CTAs/SM.
// Per-CTA pipeline in SMEM: x-tile -> QKV GEMMs -> rotary -> attention
// (decay-masked softmax over S=32) -> +res LN1 -> FFN (hidden processed in
// 128-col blocks, FFN2 accumulated in registers) -> +res LN2 -> out.

#define TS 132            // 32-row tile stride (pad 128 -> 132 floats)
#define TPB 256

__device__ __forceinline__ float4 ld4(const float* p) { return *(const float4*)p; }

// Accumulate: acc[4][4] += As[r0..r0+3][0..K) * W[0..K)[c0..c0+3]  (W row stride LDW)
template<int K, int LDW>
__device__ __forceinline__ void gemm_acc(
    const float* __restrict__ As, int lda,
    const float* __restrict__ W, int c0, int r0,
    float acc[4][4])
{
#pragma unroll 2
    for (int k = 0; k < K; k += 4) {
        float4 a0 = ld4(&As[(r0 + 0) * lda + k]);
        float4 a1 = ld4(&As[(r0 + 1) * lda + k]);
        float4 a2 = ld4(&As[(r0 + 2) * lda + k]);
        float4 a3 = ld4(&As[(r0 + 3) * lda + k]);
#pragma unroll
        for (int kk = 0; kk < 4; kk++) {
            float4 w = ld4(&W[(k + kk) * LDW + c0]);
            float a[4] = { ((const float*)&a0)[kk], ((const float*)&a1)[kk],
                           ((const float*)&a2)[kk], ((const float*)&a3)[kk] };
#pragma unroll
            for (int i = 0; i < 4; i++) {
                acc[i][0] += a[i] * w.x; acc[i][1] += a[i] * w.y;
                acc[i][2] += a[i] * w.z; acc[i][3] += a[i] * w.w;
            }
        }
    }
}

// Full 32x128-slice GEMM with bias (+optional relu) written to SMEM.
template<int K, int LDW>
__device__ __forceinline__ void gemm_32xN(
    const float* __restrict__ As, int lda,
    const float* __restrict__ W,
    const float* __restrict__ bias, int colbase,
    float* __restrict__ Os, int ldo,
    bool relu, int tr, int tc)
{
    const int r0 = tr * 4;
    const int c0 = colbase + tc * 4;
    float4 bv = ld4(&bias[c0]);
    float acc[4][4];
#pragma unroll
    for (int i = 0; i < 4; i++) {
        acc[i][0] = bv.x; acc[i][1] = bv.y; acc[i][2] = bv.z; acc[i][3] = bv.w;
    }
    gemm_acc<K, LDW>(As, lda, W, c0, r0, acc);
#pragma unroll
    for (int i = 0; i < 4; i++) {
        float4 o;
        o.x = acc[i][0]; o.y = acc[i][1]; o.z = acc[i][2]; o.w = acc[i][3];
        if (relu) {
            o.x = fmaxf(o.x, 0.f); o.y = fmaxf(o.y, 0.f);
            o.z = fmaxf(o.z, 0.f); o.w = fmaxf(o.w, 0.f);
        }
        *(float4*)&Os[(r0 + i) * ldo + tc * 4] = o;   // Os indexed by local col
    }
}

extern "C" __global__ void __launch_bounds__(TPB, 2)
retention_block_kernel(
    const float* __restrict__ x,
    const float* __restrict__ wq, const float* __restrict__ bq,
    const float* __restrict__ wk, const float* __restrict__ bk,
    const float* __restrict__ wv, const float* __restrict__ bv,
    const float* __restrict__ ln1g, const float* __restrict__ ln1b,
    const float* __restrict__ w1, const float* __restrict__ b1,
    const float* __restrict__ w2, const float* __restrict__ b2,
    const float* __restrict__ ln2g, const float* __restrict__ ln2b,
    float* __restrict__ out, int N)
{
    extern __shared__ float sm[];
    float* xs  = sm;                 // 32 x TS : x rows (residual 1)
    float* ta  = xs  + 32 * TS;      // q  -> attn_out
    float* tb  = ta  + 32 * TS;      // k  -> LN1 out (h0, residual 2)
    float* tcm = tb  + 32 * TS;      // v  -> ffn2 out
    float* hb  = tcm + 32 * TS;      // 32 x TS : FFN hidden block (reused 4x)

    const int t  = threadIdx.x;
    const int n  = blockIdx.x;
    const int tr = t >> 5, tc = t & 31;

    // ---- load x tile: xs[s][c] = x[s][n][c] ----
    {
        const float4* xg = (const float4*)x;
        for (int idx = t; idx < 32 * 32; idx += TPB) {
            int r = idx >> 5, c4 = idx & 31;
            float4 v = xg[((size_t)r * N + n) * 32 + c4];
            *(float4*)&xs[r * TS + c4 * 4] = v;
        }
    }
    __syncthreads();

    // ---- QKV projections ----
    gemm_32xN<128, 128>(xs, TS, wq, bq, 0, ta,  TS, false, tr, tc);
    gemm_32xN<128, 128>(xs, TS, wk, bk, 0, tb,  TS, false, tr, tc);
    gemm_32xN<128, 128>(xs, TS, wv, bv, 0, tcm, TS, false, tr, tc);
    __syncthreads();

    // ---- rotary on q (ta) and k (tb); each (row, head) owned by one thread ----
    {
        int r = t >> 3, h = t & 7;   // row 0..31, head 0..7
        const float l2c = 13.287712379549449f / 7.0f;   // log2(10000)/7
        float sn[16], cs[16];
#pragma unroll
        for (int d = 0; d < 16; d++) {
            float ang = exp2f(-(float)(d >> 1) * l2c);
            float ph = (float)r * ang;
            sn[d] = sinf(ph); cs[d] = cosf(ph);
        }
#pragma unroll
        for (int which = 0; which < 2; which++) {
            float* bp = (which == 0 ? ta : tb) + r * TS + h * 16;
            float tv[16];
#pragma unroll
            for (int d = 0; d < 16; d++) tv[d] = bp[d];
#pragma unroll
            for (int d = 0; d < 8; d++)  bp[d] = tv[d] * cs[d] - tv[2 * d + 1]   * sn[d];
#pragma unroll
            for (int d = 8; d < 16; d++) bp[d] = tv[d] * cs[d] + tv[2 * (d - 8)] * sn[d];
        }
    }
    __syncthreads();

    // ---- attention: warp h handles head h, lane i = query row ----
    {
        int h = t >> 5, qi = t & 31;
        float qr[16];
#pragma unroll
        for (int d4 = 0; d4 < 4; d4++) {
            float4 v = ld4(&ta[qi * TS + h * 16 + d4 * 4]);
            qr[d4 * 4 + 0] = v.x; qr[d4 * 4 + 1] = v.y;
            qr[d4 * 4 + 2] = v.z; qr[d4 * 4 + 3] = v.w;
        }
        __syncthreads();   // ta now free -> attn_out destination

        float dec = log1pf(-exp2f(-(1.0f + 0.375f * (float)h)));
        float sc[32];
#pragma unroll
        for (int j = 0; j < 32; j++) {
            const float* kp = &tb[j * TS + h * 16];
            float s = fabsf((float)(qi - j)) * dec;
#pragma unroll
            for (int d4 = 0; d4 < 4; d4++) {
                float4 kv = ld4(kp + d4 * 4);
                s += qr[d4 * 4 + 0] * kv.x + qr[d4 * 4 + 1] * kv.y
                   + qr[d4 * 4 + 2] * kv.z + qr[d4 * 4 + 3] * kv.w;
            }
            sc[j] = s;
        }
        float m = sc[0];
#pragma unroll
        for (int j = 1; j < 32; j++) m = fmaxf(m, sc[j]);
        float sum = 0.f;
#pragma unroll
        for (int j = 0; j < 32; j++) { sc[j] = __expf(sc[j] - m); sum += sc[j]; }
        float inv = 1.0f / sum;
        float o[16];
#pragma unroll
        for (int d = 0; d < 16; d++) o[d] = 0.f;
#pragma unroll
        for (int j = 0; j < 32; j++) {
            const float* vp = &tcm[j * TS + h * 16];
            float p = sc[j];
#pragma unroll
            for (int d4 = 0; d4 < 4; d4++) {
                float4 vv = ld4(vp + d4 * 4);
                o[d4 * 4 + 0] += p * vv.x; o[d4 * 4 + 1] += p * vv.y;
                o[d4 * 4 + 2] += p * vv.z; o[d4 * 4 + 3] += p * vv.w;
            }
        }
#pragma unroll
        for (int d = 0; d < 16; d++) ta[qi * TS + h * 16 + d] = o[d] * inv;
    }
    __syncthreads();

    // ---- LN1: h0 = LN(attn_out + x) -> tb ----
    {
        int w = t >> 5, l = t & 31;
        for (int r = w; r < 32; r += 8) {
            float4 a  = ld4(&ta[r * TS + 4 * l]);
            float4 xv = ld4(&xs[r * TS + 4 * l]);
            float v0 = a.x + xv.x, v1 = a.y + xv.y, v2 = a.z + xv.z, v3 = a.w + xv.w;
            float s  = v0 + v1 + v2 + v3;
            float s2 = v0 * v0 + v1 * v1 + v2 * v2 + v3 * v3;
#pragma unroll
            for (int off = 16; off; off >>= 1) {
                s  += __shfl_xor_sync(0xffffffffu, s,  off);
                s2 += __shfl_xor_sync(0xffffffffu, s2, off);
            }
            float mu  = s * (1.f / 128.f);
            float var = s2 * (1.f / 128.f) - mu * mu;
            float rs  = rsqrtf(var + 1e-5f);
            float4 gg = ld4(&ln1g[4 * l]);
            float4 bb = ld4(&ln1b[4 * l]);
            float4 o;
            o.x = (v0 - mu) * rs * gg.x + bb.x; o.y = (v1 - mu) * rs * gg.y + bb.y;
            o.z = (v2 - mu) * rs * gg.z + bb.z; o.w = (v3 - mu) * rs * gg.w + bb.w;
            *(float4*)&tb[r * TS + 4 * l] = o;
        }
    }
    __syncthreads();

    // ---- FFN fused: for each 128-col hidden block, compute relu(h0@w1+b1)
    //      into hb, then accumulate hb @ w2-block into register acc ----
    {
        const int r0 = tr * 4, c0 = tc * 4;
        float4 b2v = ld4(&b2[c0]);
        float acc[4][4];
#pragma unroll
        for (int i = 0; i < 4; i++) {
            acc[i][0] = b2v.x; acc[i][1] = b2v.y; acc[i][2] = b2v.z; acc[i][3] = b2v.w;
        }
        for (int cb = 0; cb < 4; cb++) {
            gemm_32xN<128, 512>(tb, TS, w1, b1, cb * 128, hb, TS, true, tr, tc);
            __syncthreads();
            gemm_acc<128, 128>(hb, TS, w2 + cb * 128 * 128, c0, r0, acc);
            __syncthreads();   // before hb is overwritten next iter
        }
#pragma unroll
        for (int i = 0; i < 4; i++) {
            float4 o;
            o.x = acc[i][0]; o.y = acc[i][1]; o.z = acc[i][2]; o.w = acc[i][3];
            *(float4*)&tcm[(r0 + i) * TS + c0] = o;
        }
    }
    __syncthreads();

    // ---- LN2: out = LN(ffn + h0), store transposed (s, n, c) ----
    {
        int w = t >> 5, l = t & 31;
        for (int r = w; r < 32; r += 8) {
            float4 a  = ld4(&tcm[r * TS + 4 * l]);
            float4 hv = ld4(&tb[r * TS + 4 * l]);
            float v0 = a.x + hv.x, v1 = a.y + hv.y, v2 = a.z + hv.z, v3 = a.w + hv.w;
            float s  = v0 + v1 + v2 + v3;
            float s2 = v0 * v0 + v1 * v1 + v2 * v2 + v3 * v3;
#pragma unroll
            for (int off = 16; off; off >>= 1) {
                s  += __shfl_xor_sync(0xffffffffu, s,  off);
                s2 += __shfl_xor_sync(0xffffffffu, s2, off);
            }
            float mu  = s * (1.f / 128.f);
            float var = s2 * (1.f / 128.f) - mu * mu;
            float rs  = rsqrtf(var + 1e-5f);
            float4 gg = ld4(&ln2g[4 * l]);
            float4 bb = ld4(&ln2b[4 * l]);
            float4 o;
            o.x = (v0 - mu) * rs * gg.x + bb.x; o.y = (v1 - mu) * rs * gg.y + bb.y;
            o.z = (v2 - mu) * rs * gg.z + bb.z; o.w = (v3 - mu) * rs * gg.w + bb.w;
            *(float4*)&out[((size_t)r * N + n) * 128 + 4 * l] = o;
        }
    }
}

static const int SMEM_BYTES = (5 * 32 * TS) * (int)sizeof(float);  // 84480

extern "C" void kernel_launch(void* const* d_in, const int* in_sizes, int n_in,
                              void* d_out, int out_size)
{
    const float* x    = (const float*)d_in[0];
    const float* wq   = (const float*)d_in[1];
    const float* bq   = (const float*)d_in[2];
    const float* wk   = (const float*)d_in[3];
    const float* bk   = (const float*)d_in[4];
    const float* wv   = (const float*)d_in[5];
    const float* bv   = (const float*)d_in[6];
    const float* ln1g = (const float*)d_in[7];
    const float* ln1b = (const float*)d_in[8];
    const float* w1   = (const float*)d_in[9];
    const float* b1   = (const float*)d_in[10];
    const float* w2   = (const float*)d_in[11];
    const float* b2   = (const float*)d_in[12];
    const float* ln2g = (const float*)d_in[13];
    const float* ln2b = (const float*)d_in[14];
    float* out = (float*)d_out;

    int N = in_sizes[0] / (32 * 128);   // B=32, C=128 fixed; N from x element count

    // Idempotent + deterministic on every call (no static guards; not a
    // stream-ordered op, so safe under graph capture).
    cudaFuncSetAttribute(retention_block_kernel,
                         cudaFuncAttributeMaxDynamicSharedMemorySize, SMEM_BYTES);

    retention_block_kernel<<<N, TPB, SMEM_BYTES>>>(
        x, wq, bq, wk, bk, wv, bv, ln1g, ln1b,
        w1, b1, w2, b2, ln2g, ln2b, out, N);
}